// round 9
// baseline (speedup 1.0000x reference)
#include <cuda_runtime.h>
#include <cuda_bf16.h>
#include <cstdint>

// ---------------------------------------------------------------------------
// TensorNet interaction.
//   msg[n] = (component tensors of n) * (per-node scalar sums of edge MLP),
//   so the graph part is a scatter-add of 96 edge-MLP outputs into acc[n][96].
//
// R9: edge scatter upgraded from red.v2 to red.v4 via lane pairing
//     (shfl_xor(1) within each quad assembles 4 consecutive columns; even
//     lane scatters rowA, odd lane rowB). REDG lane-ops halve. Edge kernel
//     was REDG-bound (~92us of LSU lane time at v2). Node kernel unchanged
//     (R8 in-place MMA mixing).
// ---------------------------------------------------------------------------

#define MAXN 50000
#define PI_F 3.14159265358979323846f
#define CUTOFF_F 5.0f

__device__ float g_acc[(size_t)MAXN * 96];

__device__ __forceinline__ float silu_f(float v) {
    return v * __fdividef(1.0f, 1.0f + __expf(-v));
}
__device__ __forceinline__ uint32_t packbf(float lo, float hi) {
    uint32_t r;
    asm("cvt.rn.bf16x2.f32 %0, %1, %2;" : "=r"(r) : "f"(hi), "f"(lo));
    return r;
}
__device__ __forceinline__ float bf16val(float v) {
    return __bfloat162float(__float2bfloat16(v));
}
__device__ __forceinline__ void pack_hl(float x, float y, uint32_t& h, uint32_t& l) {
    h = packbf(x, y);
    l = packbf(x - bf16val(x), y - bf16val(y));
}
__device__ __forceinline__ void mma_bf16(float c[4], const uint32_t a[4], uint2 b) {
    asm volatile(
        "mma.sync.aligned.m16n8k16.row.col.f32.bf16.bf16.f32 "
        "{%0,%1,%2,%3}, {%4,%5,%6,%7}, {%8,%9}, {%0,%1,%2,%3};"
        : "+f"(c[0]), "+f"(c[1]), "+f"(c[2]), "+f"(c[3])
        : "r"(a[0]), "r"(a[1]), "r"(a[2]), "r"(a[3]), "r"(b.x), "r"(b.y));
}

// ---------------------------------------------------------------------------
// Edge MLP kernel. Warp = 16-edge strip.
__global__ void __launch_bounds__(256)
edge_mma_kernel(const float* __restrict__ edge_attr,
                const int*   __restrict__ edge_index,
                const float* __restrict__ edge_weight,
                const float* __restrict__ W1, const float* __restrict__ b1,
                const float* __restrict__ W2, const float* __restrict__ b2,
                const float* __restrict__ W3, const float* __restrict__ b3,
                int E)
{
    __shared__ uint2 sB1h[8][32],  sB1l[8][32];
    __shared__ uint2 sB2h[16][32], sB2l[16][32];
    __shared__ uint2 sB3h[48][32], sB3l[48][32];
    __shared__ float sb1[32], sb2[64], sb3[96];

    const int tid = threadIdx.x;

    {
        int i = tid;
        int f = i >> 5, l = i & 31;
        int nt = f >> 1, kf = f & 1;
        int n = nt * 8 + (l >> 2), k0 = kf * 16 + ((l & 3) << 1);
        const float* Wr = W1 + n * 32 + k0;
        uint32_t h0, l0, h1, l1;
        pack_hl(Wr[0], Wr[1], h0, l0);
        pack_hl(Wr[8], Wr[9], h1, l1);
        sB1h[f][l] = make_uint2(h0, h1);
        sB1l[f][l] = make_uint2(l0, l1);
    }
    for (int i = tid; i < 512; i += 256) {
        int f = i >> 5, l = i & 31;
        int nt = f >> 1, kf = f & 1;
        int n = nt * 8 + (l >> 2), k0 = kf * 16 + ((l & 3) << 1);
        const float* Wr = W2 + n * 32 + k0;
        uint32_t h0, l0, h1, l1;
        pack_hl(Wr[0], Wr[1], h0, l0);
        pack_hl(Wr[8], Wr[9], h1, l1);
        sB2h[f][l] = make_uint2(h0, h1);
        sB2l[f][l] = make_uint2(l0, l1);
    }
    for (int i = tid; i < 1536; i += 256) {
        int f = i >> 5, l = i & 31;
        int nt = f >> 2, kf = f & 3;
        int n = nt * 8 + (l >> 2), k0 = kf * 16 + ((l & 3) << 1);
        const float* Wr = W3 + n * 64 + k0;
        uint32_t h0, l0, h1, l1;
        pack_hl(Wr[0], Wr[1], h0, l0);
        pack_hl(Wr[8], Wr[9], h1, l1);
        sB3h[f][l] = make_uint2(h0, h1);
        sB3l[f][l] = make_uint2(l0, l1);
    }
    if (tid < 32) sb1[tid] = b1[tid];
    if (tid < 64) sb2[tid] = b2[tid];
    if (tid < 96) sb3[tid] = b3[tid];
    __syncthreads();

    const int wid = tid >> 5, lane = tid & 31;
    const int r1 = lane >> 2;
    const int tig = lane & 3;
    const int q  = tig << 1;
    const int nStrips = (E + 15) >> 4;

    for (int strip = blockIdx.x * 8 + wid; strip < nStrips;
         strip += gridDim.x * 8) {
        int e0 = strip << 4;
        int eA = e0 + r1, eB = eA + 8;
        int eAc = min(eA, E - 1), eBc = min(eB, E - 1);

        uint32_t A1h[2][4], A1l[2][4];
        #pragma unroll
        for (int kf = 0; kf < 2; kf++) {
            const float* pa = edge_attr + (size_t)eAc * 32 + kf * 16 + q;
            const float* pb = edge_attr + (size_t)eBc * 32 + kf * 16 + q;
            float2 v0 = *(const float2*)pa;
            float2 v1 = *(const float2*)pb;
            float2 v2 = *(const float2*)(pa + 8);
            float2 v3 = *(const float2*)(pb + 8);
            pack_hl(v0.x, v0.y, A1h[kf][0], A1l[kf][0]);
            pack_hl(v1.x, v1.y, A1h[kf][1], A1l[kf][1]);
            pack_hl(v2.x, v2.y, A1h[kf][2], A1l[kf][2]);
            pack_hl(v3.x, v3.y, A1h[kf][3], A1l[kf][3]);
        }

        float D1[4][4];
        #pragma unroll
        for (int nt = 0; nt < 4; nt++) {
            float bb0 = sb1[nt * 8 + q], bb1 = sb1[nt * 8 + q + 1];
            D1[nt][0] = bb0; D1[nt][1] = bb1; D1[nt][2] = bb0; D1[nt][3] = bb1;
            #pragma unroll
            for (int kf = 0; kf < 2; kf++) {
                uint2 Bh = sB1h[nt * 2 + kf][lane];
                uint2 Bl = sB1l[nt * 2 + kf][lane];
                mma_bf16(D1[nt], A1h[kf], Bh);
                mma_bf16(D1[nt], A1l[kf], Bh);
                mma_bf16(D1[nt], A1h[kf], Bl);
            }
        }

        uint32_t A2h[2][4], A2l[2][4];
        #pragma unroll
        for (int kf = 0; kf < 2; kf++) {
            int na = 2 * kf, nb = 2 * kf + 1;
            float sa0 = silu_f(D1[na][0]), sa1 = silu_f(D1[na][1]);
            float sa2 = silu_f(D1[na][2]), sa3 = silu_f(D1[na][3]);
            float sb0 = silu_f(D1[nb][0]), sb1v = silu_f(D1[nb][1]);
            float sb2v = silu_f(D1[nb][2]), sb3v = silu_f(D1[nb][3]);
            pack_hl(sa0, sa1, A2h[kf][0], A2l[kf][0]);
            pack_hl(sa2, sa3, A2h[kf][1], A2l[kf][1]);
            pack_hl(sb0, sb1v, A2h[kf][2], A2l[kf][2]);
            pack_hl(sb2v, sb3v, A2h[kf][3], A2l[kf][3]);
        }

        float D2[8][4];
        #pragma unroll
        for (int nt = 0; nt < 8; nt++) {
            float bb0 = sb2[nt * 8 + q], bb1 = sb2[nt * 8 + q + 1];
            D2[nt][0] = bb0; D2[nt][1] = bb1; D2[nt][2] = bb0; D2[nt][3] = bb1;
            #pragma unroll
            for (int kf = 0; kf < 2; kf++) {
                uint2 Bh = sB2h[nt * 2 + kf][lane];
                uint2 Bl = sB2l[nt * 2 + kf][lane];
                mma_bf16(D2[nt], A2h[kf], Bh);
                mma_bf16(D2[nt], A2l[kf], Bh);
                mma_bf16(D2[nt], A2h[kf], Bl);
            }
        }

        uint32_t A3h[4][4], A3l[4][4];
        #pragma unroll
        for (int kf = 0; kf < 4; kf++) {
            int na = 2 * kf, nb = 2 * kf + 1;
            float sa0 = silu_f(D2[na][0]), sa1 = silu_f(D2[na][1]);
            float sa2 = silu_f(D2[na][2]), sa3 = silu_f(D2[na][3]);
            float sb0 = silu_f(D2[nb][0]), sb1v = silu_f(D2[nb][1]);
            float sb2v = silu_f(D2[nb][2]), sb3v = silu_f(D2[nb][3]);
            pack_hl(sa0, sa1, A3h[kf][0], A3l[kf][0]);
            pack_hl(sa2, sa3, A3h[kf][1], A3l[kf][1]);
            pack_hl(sb0, sb1v, A3h[kf][2], A3l[kf][2]);
            pack_hl(sb2v, sb3v, A3h[kf][3], A3l[kf][3]);
        }

        float D3[12][4];
        #pragma unroll
        for (int nt = 0; nt < 12; nt++) {
            float bb0 = sb3[nt * 8 + q], bb1 = sb3[nt * 8 + q + 1];
            D3[nt][0] = bb0; D3[nt][1] = bb1; D3[nt][2] = bb0; D3[nt][3] = bb1;
            #pragma unroll
            for (int kf = 0; kf < 4; kf++) {
                uint2 Bh = sB3h[nt * 4 + kf][lane];
                uint2 Bl = sB3l[nt * 4 + kf][lane];
                mma_bf16(D3[nt], A3h[kf], Bh);
                mma_bf16(D3[nt], A3l[kf], Bh);
                mma_bf16(D3[nt], A3h[kf], Bl);
            }
        }

        // ---- epilogue: silu*Cc, pair lanes -> red.v4 scatter ----
        float wA = edge_weight[eAc], wB = edge_weight[eBc];
        float CcA = (wA < CUTOFF_F)
                  ? 0.5f * (__cosf(wA * (PI_F / CUTOFF_F)) + 1.0f) : 0.0f;
        float CcB = (wB < CUTOFF_F)
                  ? 0.5f * (__cosf(wB * (PI_F / CUTOFF_F)) + 1.0f) : 0.0f;
        int dA = edge_index[E + eAc], dB = edge_index[E + eBc];
        bool okA = eA < E, okB = eB < E;

        // even lane of each pair scatters rowA (4 consecutive cols),
        // odd lane scatters rowB. colbase = 4*(tig>>1).
        int colbase = (tig >> 1) << 2;
        bool isEven = (tig & 1) == 0;
        float* gP = g_acc + (isEven ? (size_t)dA : (size_t)dB) * 96 + colbase;
        bool ok = isEven ? okA : okB;

        #pragma unroll
        for (int nt = 0; nt < 12; nt++) {
            float t0 = silu_f(D3[nt][0]) * CcA;   // rowA cols q,q+1
            float t1 = silu_f(D3[nt][1]) * CcA;
            float t2 = silu_f(D3[nt][2]) * CcB;   // rowB cols q,q+1
            float t3 = silu_f(D3[nt][3]) * CcB;
            float p0 = __shfl_xor_sync(0xFFFFFFFFu, t0, 1);
            float p1 = __shfl_xor_sync(0xFFFFFFFFu, t1, 1);
            float p2 = __shfl_xor_sync(0xFFFFFFFFu, t2, 1);
            float p3 = __shfl_xor_sync(0xFFFFFFFFu, t3, 1);
            // even lane: rowA = (t0,t1, p0,p1)  (own cols 4t..4t+1, partner 4t+2..4t+3)
            // odd  lane: rowB = (p2,p3, t2,t3)  (partner cols 4t..4t+1, own 4t+2..4t+3)
            float v0 = isEven ? t0 : p2;
            float v1 = isEven ? t1 : p3;
            float v2 = isEven ? p0 : t2;
            float v3 = isEven ? p1 : t3;
            if (ok) {
                asm volatile("red.global.add.v4.f32 [%0], {%1, %2, %3, %4};"
                             :: "l"(gP + nt * 8),
                                "f"(v0), "f"(v1), "f"(v2), "f"(v3) : "memory");
            }
        }
    }
}

// ---------------------------------------------------------------------------
// Node kernel, MMA mixing, in-place c/r buffer (unchanged from R8).
#define RS 36   // row stride in floats

__global__ void __launch_bounds__(256)
node_mma_kernel(const float* __restrict__ X,
                const float* __restrict__ Wt,
                float* __restrict__ out,
                int nNodes, int nStrips)
{
    extern __shared__ char smem[];
    uint2* sBh  = (uint2*)smem;
    uint2* sBl  = (uint2*)(smem + 12288);
    float* cr   = (float*)(smem + 24576);

    const int tid  = threadIdx.x;
    const int lane = tid & 31, wid = tid >> 5;
    const int gr   = lane >> 2, tig = lane & 3;

    for (int i = tid; i < 1536; i += 256) {
        int mat = i >> 8, rem = i & 255;
        int f = rem >> 5, l = rem & 31;
        int nt = f >> 1, kf = f & 1;
        int n = nt * 8 + (l >> 2), k0 = kf * 16 + ((l & 3) << 1);
        const float* Wr = Wt + mat * 1024 + n * 32 + k0;
        uint32_t h0, l0, h1, l1;
        pack_hl(Wr[0], Wr[1], h0, l0);
        pack_hl(Wr[8], Wr[9], h1, l1);
        sBh[i] = make_uint2(h0, h1);
        sBl[i] = make_uint2(l0, l1);
    }
    __syncthreads();

    const int nl0 = tid >> 5;
    const int u   = lane;

    for (int s = blockIdx.x; s < nStrips; s += gridDim.x) {
        const int nodeBase = s << 4;
        float Xn[2][9];

        #pragma unroll
        for (int cc = 0; cc < 2; cc++) {
            int r0 = nl0 + cc * 8;
            int n  = nodeBase + r0;
            int nc = min(n, nNodes - 1);
            float nrm = 1.0f;
            #pragma unroll
            for (int t = 0; t < 9; t++) {
                float v = X[((size_t)nc * 9 + t) * 32 + u];
                Xn[cc][t] = v; nrm += v * v;
            }
            float inv = __fdividef(1.0f, nrm);
            #pragma unroll
            for (int t = 0; t < 9; t++) Xn[cc][t] *= inv;

            const float* x = Xn[cc];
            float tr3 = (x[0] + x[4] + x[8]) * (1.0f / 3.0f);
            float* cp = cr + r0 * RS + u;
            cp[0 * 16 * RS] = tr3;
            cp[1 * 16 * RS] = 0.5f * (x[1] - x[3]);
            cp[2 * 16 * RS] = 0.5f * (x[2] - x[6]);
            cp[3 * 16 * RS] = 0.5f * (x[5] - x[7]);
            cp[4 * 16 * RS] = x[0] - tr3;
            cp[5 * 16 * RS] = 0.5f * (x[1] + x[3]);
            cp[6 * 16 * RS] = 0.5f * (x[2] + x[6]);
            cp[7 * 16 * RS] = x[4] - tr3;
            cp[8 * 16 * RS] = 0.5f * (x[5] + x[7]);
        }
        __syncthreads();

        #pragma unroll 1
        for (int rt = wid; rt < 9; rt += 8) {
            int mat = (rt == 0) ? 0 : (rt < 4) ? 1 : 2;
            const float* crow0 = cr + (16 * rt + gr) * RS;
            const float* crow1 = crow0 + 8 * RS;
            uint32_t Ah[2][4], Al[2][4];
            #pragma unroll
            for (int kf = 0; kf < 2; kf++) {
                int c0 = kf * 16 + 2 * tig;
                float2 v0 = *(const float2*)(crow0 + c0);
                float2 v1 = *(const float2*)(crow1 + c0);
                float2 v2 = *(const float2*)(crow0 + c0 + 8);
                float2 v3 = *(const float2*)(crow1 + c0 + 8);
                pack_hl(v0.x, v0.y, Ah[kf][0], Al[kf][0]);
                pack_hl(v1.x, v1.y, Ah[kf][1], Al[kf][1]);
                pack_hl(v2.x, v2.y, Ah[kf][2], Al[kf][2]);
                pack_hl(v3.x, v3.y, Ah[kf][3], Al[kf][3]);
            }
            float D[4][4];
            #pragma unroll
            for (int nt = 0; nt < 4; nt++) {
                D[nt][0] = 0.f; D[nt][1] = 0.f; D[nt][2] = 0.f; D[nt][3] = 0.f;
                #pragma unroll
                for (int kf = 0; kf < 2; kf++) {
                    uint2 Bh = sBh[mat * 256 + (nt * 2 + kf) * 32 + lane];
                    uint2 Bl = sBl[mat * 256 + (nt * 2 + kf) * 32 + lane];
                    mma_bf16(D[nt], Ah[kf], Bh);
                    mma_bf16(D[nt], Al[kf], Bh);
                    mma_bf16(D[nt], Ah[kf], Bl);
                }
            }
            float* wr0 = cr + (16 * rt + gr) * RS + 2 * tig;
            float* wr1 = wr0 + 8 * RS;
            #pragma unroll
            for (int nt = 0; nt < 4; nt++) {
                *(float2*)(wr0 + nt * 8) = make_float2(D[nt][0], D[nt][1]);
                *(float2*)(wr1 + nt * 8) = make_float2(D[nt][2], D[nt][3]);
            }
        }
        __syncthreads();

        #pragma unroll
        for (int cc = 0; cc < 2; cc++) {
            int r0 = nl0 + cc * 8;
            int n  = nodeBase + r0;
            float* rp = cr + r0 * RS + u;
            float Ip  = rp[0 * 16 * RS];
            float a01 = rp[1 * 16 * RS];
            float a02 = rp[2 * 16 * RS];
            float a12 = rp[3 * 16 * RS];
            float s00 = rp[4 * 16 * RS];
            float s01 = rp[5 * 16 * RS];
            float s02 = rp[6 * 16 * RS];
            float s11 = rp[7 * 16 * RS];
            float s12 = rp[8 * 16 * RS];
            float s22 = -(s00 + s11);

            float sI = 0.f, sA = 0.f, sS = 0.f;
            if (n < nNodes) {
                float* ap = g_acc + (size_t)n * 96 + u * 3;
                sI = ap[0]; sA = ap[1]; sS = ap[2];
                ap[0] = 0.f; ap[1] = 0.f; ap[2] = 0.f;
            }

            float Y[9], G[9];
            Y[0] = Ip + s00;  Y[1] = a01 + s01;  Y[2] = a02 + s02;
            Y[3] = s01 - a01; Y[4] = Ip + s11;   Y[5] = a12 + s12;
            Y[6] = s02 - a02; Y[7] = s12 - a12;  Y[8] = Ip + s22;
            G[0] = Ip*sI + s00*sS;  G[1] = a01*sA + s01*sS;  G[2] = a02*sA + s02*sS;
            G[3] = s01*sS - a01*sA; G[4] = Ip*sI + s11*sS;   G[5] = a12*sA + s12*sS;
            G[6] = s02*sS - a02*sA; G[7] = s12*sS - a12*sA;  G[8] = Ip*sI + s22*sS;

            float M[9];
            #pragma unroll
            for (int i = 0; i < 3; i++)
                #pragma unroll
                for (int l = 0; l < 3; l++) {
                    float a2 = 0.0f;
                    #pragma unroll
                    for (int j = 0; j < 3; j++)
                        a2 += Y[i*3+j] * G[j*3+l] + G[i*3+j] * Y[j*3+l];
                    M[i*3+l] = a2;
                }

            float np = 1.0f;
            #pragma unroll
            for (int t = 0; t < 9; t++) np += M[t] * M[t];
            float inv2 = __fdividef(1.0f, np);
            float trm = (M[0] + M[4] + M[8]) * (1.0f / 3.0f);

            rp[0 * 16 * RS] = trm * inv2;
            rp[1 * 16 * RS] = 0.5f * (M[1] - M[3]) * inv2;
            rp[2 * 16 * RS] = 0.5f * (M[2] - M[6]) * inv2;
            rp[3 * 16 * RS] = 0.5f * (M[5] - M[7]) * inv2;
            rp[4 * 16 * RS] = (M[0] - trm) * inv2;
            rp[5 * 16 * RS] = 0.5f * (M[1] + M[3]) * inv2;
            rp[6 * 16 * RS] = 0.5f * (M[2] + M[6]) * inv2;
            rp[7 * 16 * RS] = (M[4] - trm) * inv2;
            rp[8 * 16 * RS] = 0.5f * (M[5] + M[7]) * inv2;
        }
        __syncthreads();

        #pragma unroll 1
        for (int rt = wid; rt < 9; rt += 8) {
            int mat = 3 + ((rt == 0) ? 0 : (rt < 4) ? 1 : 2);
            const float* crow0 = cr + (16 * rt + gr) * RS;
            const float* crow1 = crow0 + 8 * RS;
            uint32_t Ah[2][4], Al[2][4];
            #pragma unroll
            for (int kf = 0; kf < 2; kf++) {
                int c0 = kf * 16 + 2 * tig;
                float2 v0 = *(const float2*)(crow0 + c0);
                float2 v1 = *(const float2*)(crow1 + c0);
                float2 v2 = *(const float2*)(crow0 + c0 + 8);
                float2 v3 = *(const float2*)(crow1 + c0 + 8);
                pack_hl(v0.x, v0.y, Ah[kf][0], Al[kf][0]);
                pack_hl(v1.x, v1.y, Ah[kf][1], Al[kf][1]);
                pack_hl(v2.x, v2.y, Ah[kf][2], Al[kf][2]);
                pack_hl(v3.x, v3.y, Ah[kf][3], Al[kf][3]);
            }
            float D[4][4];
            #pragma unroll
            for (int nt = 0; nt < 4; nt++) {
                D[nt][0] = 0.f; D[nt][1] = 0.f; D[nt][2] = 0.f; D[nt][3] = 0.f;
                #pragma unroll
                for (int kf = 0; kf < 2; kf++) {
                    uint2 Bh = sBh[mat * 256 + (nt * 2 + kf) * 32 + lane];
                    uint2 Bl = sBl[mat * 256 + (nt * 2 + kf) * 32 + lane];
                    mma_bf16(D[nt], Ah[kf], Bh);
                    mma_bf16(D[nt], Al[kf], Bh);
                    mma_bf16(D[nt], Ah[kf], Bl);
                }
            }
            float* wr0 = cr + (16 * rt + gr) * RS + 2 * tig;
            float* wr1 = wr0 + 8 * RS;
            #pragma unroll
            for (int nt = 0; nt < 4; nt++) {
                *(float2*)(wr0 + nt * 8) = make_float2(D[nt][0], D[nt][1]);
                *(float2*)(wr1 + nt * 8) = make_float2(D[nt][2], D[nt][3]);
            }
        }
        __syncthreads();

        #pragma unroll
        for (int cc = 0; cc < 2; cc++) {
            int r0 = nl0 + cc * 8;
            int n  = nodeBase + r0;
            const float* rp = cr + r0 * RS + u;
            float Ip2 = rp[0 * 16 * RS];
            float b01 = rp[1 * 16 * RS];
            float b02 = rp[2 * 16 * RS];
            float b12 = rp[3 * 16 * RS];
            float t00 = rp[4 * 16 * RS];
            float t01 = rp[5 * 16 * RS];
            float t02 = rp[6 * 16 * RS];
            float t11 = rp[7 * 16 * RS];
            float t12 = rp[8 * 16 * RS];
            float t22 = -(t00 + t11);

            float D[9];
            D[0] = Ip2 + t00;  D[1] = b01 + t01;  D[2] = b02 + t02;
            D[3] = t01 - b01;  D[4] = Ip2 + t11;  D[5] = b12 + t12;
            D[6] = t02 - b02;  D[7] = t12 - b12;  D[8] = Ip2 + t22;

            if (n < nNodes) {
                #pragma unroll
                for (int i = 0; i < 3; i++)
                    #pragma unroll
                    for (int l = 0; l < 3; l++) {
                        float o = Xn[cc][i*3+l] + D[i*3+l];
                        #pragma unroll
                        for (int j = 0; j < 3; j++)
                            o += D[i*3+j] * D[j*3+l];
                        out[((size_t)n * 9 + (i*3+l)) * 32 + u] = o;
                    }
            }
        }
        __syncthreads();
    }
}

// ---------------------------------------------------------------------------
extern "C" void kernel_launch(void* const* d_in, const int* in_sizes, int n_in,
                              void* d_out, int out_size)
{
    const float* X           = (const float*)d_in[0];
    const int*   edge_index  = (const int*)  d_in[1];
    const float* edge_weight = (const float*)d_in[2];
    const float* edge_attr   = (const float*)d_in[3];
    const float* W1 = (const float*)d_in[4];
    const float* b1 = (const float*)d_in[5];
    const float* W2 = (const float*)d_in[6];
    const float* b2 = (const float*)d_in[7];
    const float* W3 = (const float*)d_in[8];
    const float* b3 = (const float*)d_in[9];
    const float* Wt = (const float*)d_in[10];
    float* out = (float*)d_out;

    int N = in_sizes[0] / 288;   // X is (N,3,3,32)
    if (N > MAXN) N = MAXN;
    int E = in_sizes[2];         // edge_weight is (E,)

    int nStrips = (E + 15) >> 4;
    int grid = (nStrips + 7) / 8;
    if (grid > 296) grid = 296;

    edge_mma_kernel<<<grid, 256>>>(
        edge_attr, edge_index, edge_weight, W1, b1, W2, b2, W3, b3, E);

    int nodeSmem = 24576 + 144 * RS * 4;   // 45312 bytes
    static bool attr_set = false;
    if (!attr_set) {
        cudaFuncSetAttribute(node_mma_kernel,
                             cudaFuncAttributeMaxDynamicSharedMemorySize, nodeSmem);
        attr_set = true;
    }
    int nodeStrips = (N + 15) / 16;
    int nodeGrid = nodeStrips < 592 ? nodeStrips : 592;
    node_mma_kernel<<<nodeGrid, 256, nodeSmem>>>(X, Wt, out, N, nodeStrips);
}